// round 7
// baseline (speedup 1.0000x reference)
#include <cuda_runtime.h>

#define IMG_H 512
#define IMG_W 512
#define TW 128                    // output tile width
#define TH 16                     // output tile height (2 CTAs/SM)
#define HALO 5
#define RAW_W 144                 // TW + 2*HALO = 138, padded
#define RAW_H (TH + 2*HALO)       // 26
#define NF 5
#define NTHREADS 512

typedef unsigned long long u64;

// ---- packed f32x2 primitives (sm_100+: FFMA2/FMUL2/FADD2 in SASS) ----
__device__ __forceinline__ u64 pack2(float lo, float hi) {
    u64 r;
    asm("mov.b64 %0, {%1, %2};" : "=l"(r) : "r"(__float_as_uint(lo)), "r"(__float_as_uint(hi)));
    return r;
}
__device__ __forceinline__ void unpack2(u64 v, float& lo, float& hi) {
    unsigned a, b;
    asm("mov.b64 {%0, %1}, %2;" : "=r"(a), "=r"(b) : "l"(v));
    lo = __uint_as_float(a); hi = __uint_as_float(b);
}
__device__ __forceinline__ u64 fma2(u64 a, u64 b, u64 c) {
    u64 d;
    asm("fma.rn.f32x2 %0, %1, %2, %3;" : "=l"(d) : "l"(a), "l"(b), "l"(c));
    return d;
}
__device__ __forceinline__ u64 mul2(u64 a, u64 b) {
    u64 d;
    asm("mul.rn.f32x2 %0, %1, %2;" : "=l"(d) : "l"(a), "l"(b));
    return d;
}
__device__ __forceinline__ u64 add2(u64 a, u64 b) {
    u64 d;
    asm("add.rn.f32x2 %0, %1, %2;" : "=l"(d) : "l"(a), "l"(b));
    return d;
}

// Normalized 1D Gaussian, ws=11, sigma=1.5
__device__ __forceinline__ float gtap(int k) {
    constexpr float G[11] = {
        0.00102838f, 0.00759876f, 0.03600077f, 0.10936071f, 0.21300554f,
        0.26601172f,
        0.21300554f, 0.10936071f, 0.03600077f, 0.00759876f, 0.00102838f
    };
    return G[k];
}
__device__ __forceinline__ u64 ggk(int k) { return pack2(gtap(k), gtap(k)); }

// reflect (mirror, no edge repeat) -- matches jnp.pad(mode='reflect')
__device__ __forceinline__ int reflect_idx(int i, int n) {
    i = (i < 0) ? -i : i;
    i = (i >= n) ? (2 * n - 2 - i) : i;
    return i;
}

__global__ void __launch_bounds__(NTHREADS, 2)
ssim_kernel(const float* __restrict__ img1, const float* __restrict__ img2,
            float* __restrict__ out)
{
    extern __shared__ float sm[];
    float* raw1 = sm;                           // [RAW_H][RAW_W]
    float* raw2 = sm + RAW_H * RAW_W;
    float* hb   = sm + 2 * RAW_H * RAW_W;       // [NF][RAW_H][TW]

    const int tx0 = blockIdx.x * TW;
    const int ty0 = blockIdx.y * TH;
    const long long planeOff = (long long)blockIdx.z * (IMG_H * IMG_W);
    const float* p1 = img1 + planeOff;
    const float* p2 = img2 + planeOff;
    const int t = threadIdx.x;

    // ---------------- Phase 0: stage raw tiles (reflect halo) ----------------
    for (int idx = t; idx < RAW_H * RAW_W; idx += NTHREADS) {
        int r = idx / RAW_W;
        int c = idx - r * RAW_W;
        int gy = reflect_idx(ty0 + r - HALO, IMG_H);
        int gx = reflect_idx(tx0 + c - HALO, IMG_W);
        long long g = (long long)gy * IMG_W + gx;
        raw1[idx] = p1[g];
        raw2[idx] = p2[g];
    }
    __syncthreads();

    // ---------------- Phase 1: horizontal 11-tap conv, packed f32x2 ----------
    // Task = 4 output cols of one raw row = 2 packed pairs per field.
    for (int idx = t; idx < RAW_H * (TW / 4); idx += NTHREADS) {
        int rr = idx >> 5;              // / 32
        int c  = (idx & 31) << 2;
        const float4* r1 = (const float4*)(raw1 + rr * RAW_W + c);
        const float4* r2 = (const float4*)(raw2 + rr * RAW_W + c);
        float x1[16], x2[16];
        #pragma unroll
        for (int q = 0; q < 4; ++q) {
            float4 v1 = r1[q], v2 = r2[q];
            x1[4*q+0] = v1.x; x1[4*q+1] = v1.y; x1[4*q+2] = v1.z; x1[4*q+3] = v1.w;
            x2[4*q+0] = v2.x; x2[4*q+1] = v2.y; x2[4*q+2] = v2.z; x2[4*q+3] = v2.w;
        }
        u64 s1a = 0, s1b = 0, s2a = 0, s2b = 0;
        u64 s11a = 0, s11b = 0, s22a = 0, s22b = 0, s12a = 0, s12b = 0;
        #pragma unroll
        for (int k = 0; k < 11; ++k) {
            const u64 g = ggk(k);
            u64 pa = pack2(x1[k],     x1[k + 1]);
            u64 pb = pack2(x1[k + 2], x1[k + 3]);
            u64 qa = pack2(x2[k],     x2[k + 1]);
            u64 qb = pack2(x2[k + 2], x2[k + 3]);
            s1a  = fma2(g, pa, s1a);            s1b  = fma2(g, pb, s1b);
            s2a  = fma2(g, qa, s2a);            s2b  = fma2(g, qb, s2b);
            s11a = fma2(g, mul2(pa, pa), s11a); s11b = fma2(g, mul2(pb, pb), s11b);
            s22a = fma2(g, mul2(qa, qa), s22a); s22b = fma2(g, mul2(qb, qb), s22b);
            s12a = fma2(g, mul2(pa, qa), s12a); s12b = fma2(g, mul2(pb, qb), s12b);
        }
        float* hp = hb + rr * TW + c;
        *(u64*)(hp + 0 * RAW_H * TW)     = s1a;  *(u64*)(hp + 0 * RAW_H * TW + 2) = s1b;
        *(u64*)(hp + 1 * RAW_H * TW)     = s2a;  *(u64*)(hp + 1 * RAW_H * TW + 2) = s2b;
        *(u64*)(hp + 2 * RAW_H * TW)     = s11a; *(u64*)(hp + 2 * RAW_H * TW + 2) = s11b;
        *(u64*)(hp + 3 * RAW_H * TW)     = s22a; *(u64*)(hp + 3 * RAW_H * TW + 2) = s22b;
        *(u64*)(hp + 4 * RAW_H * TW)     = s12a; *(u64*)(hp + 4 * RAW_H * TW + 2) = s12b;
    }
    __syncthreads();

    // ------------- Phase 2: vertical conv + epilogue, column-pair packed ------
    // 64 col-pairs x 8 row-groups(2 rows) = exactly 512 tasks, LDS.64 operands.
    {
        const int p  = t & 63;              // column pair -> cols 2p, 2p+1
        const int r0 = (t >> 6) << 1;       // 0,2,...,14
        const float* hbase = hb + r0 * TW + 2 * p;

        u64 acc[NF][2];
        #pragma unroll
        for (int f = 0; f < NF; ++f) { acc[f][0] = 0; acc[f][1] = 0; }

        #pragma unroll
        for (int rr = 0; rr < 12; ++rr) {
            #pragma unroll
            for (int f = 0; f < NF; ++f) {
                u64 v = *(const u64*)(hbase + (f * RAW_H + rr) * TW);
                if (rr <= 10) acc[f][0] = fma2(ggk(rr), v, acc[f][0]);
                if (rr >= 1)  acc[f][1] = fma2(ggk(rr - 1), v, acc[f][1]);
            }
        }

        const u64 c1P  = pack2(1.0e-4f, 1.0e-4f);
        const u64 c2P  = pack2(9.0e-4f, 9.0e-4f);
        const u64 twoP = pack2(2.f, 2.f);
        const u64 negP = pack2(-1.f, -1.f);
        float* op = out + planeOff + (long long)(ty0 + r0) * IMG_W + tx0 + 2 * p;
        #pragma unroll
        for (int i = 0; i < 2; ++i) {
            u64 mu1 = acc[0][i], mu2 = acc[1][i];
            u64 m11 = mul2(mu1, mu1), m22 = mul2(mu2, mu2), m12 = mul2(mu1, mu2);
            u64 sg1  = fma2(m11, negP, acc[2][i]);
            u64 sg2  = fma2(m22, negP, acc[3][i]);
            u64 sg12 = fma2(m12, negP, acc[4][i]);
            u64 num  = mul2(fma2(twoP, m12, c1P), fma2(twoP, sg12, c2P));
            u64 den  = mul2(add2(add2(m11, m22), c1P), add2(add2(sg1, sg2), c2P));
            float nlo, nhi, dlo, dhi;
            unpack2(num, nlo, nhi);
            unpack2(den, dlo, dhi);
            float2 o;
            o.x = __fdividef(nlo, dlo);
            o.y = __fdividef(nhi, dhi);
            *(float2*)(op + (long long)i * IMG_W) = o;
        }
    }
}

extern "C" void kernel_launch(void* const* d_in, const int* in_sizes, int n_in,
                              void* d_out, int out_size) {
    const float* img1 = (const float*)d_in[0];
    const float* img2 = (const float*)d_in[1];
    // d_in[2] (11x11 gaussian window) is a fixed function of ws=11, sigma=1.5,
    // baked in as immediates.
    float* out = (float*)d_out;

    const int planes = out_size / (IMG_H * IMG_W);   // 48
    constexpr int SMEM = (2 * RAW_H * RAW_W + NF * RAW_H * TW) * (int)sizeof(float);
    cudaFuncSetAttribute(ssim_kernel,
                         cudaFuncAttributeMaxDynamicSharedMemorySize, SMEM);
    dim3 grid(IMG_W / TW, IMG_H / TH, planes);
    ssim_kernel<<<grid, NTHREADS, SMEM>>>(img1, img2, out);
}

// round 8
// speedup vs baseline: 1.0065x; 1.0065x over previous
#include <cuda_runtime.h>

#define IMG_H 512
#define IMG_W 512
#define TW 128                    // output tile width
#define TH 16                     // output tile height (2 CTAs/SM)
#define HALO 5
#define RAW_W 144                 // TW + 2*HALO = 138, padded
#define RAW_H (TH + 2*HALO)       // 26
#define NF 5
#define NTHREADS 512

typedef unsigned long long u64;

// ---- packed f32x2 primitives (sm_100+: FFMA2/FMUL2/FADD2 in SASS) ----
__device__ __forceinline__ u64 pack2(float lo, float hi) {
    u64 r;
    asm("mov.b64 %0, {%1, %2};" : "=l"(r) : "r"(__float_as_uint(lo)), "r"(__float_as_uint(hi)));
    return r;
}
__device__ __forceinline__ void unpack2(u64 v, float& lo, float& hi) {
    unsigned a, b;
    asm("mov.b64 {%0, %1}, %2;" : "=r"(a), "=r"(b) : "l"(v));
    lo = __uint_as_float(a); hi = __uint_as_float(b);
}
__device__ __forceinline__ u64 fma2(u64 a, u64 b, u64 c) {
    u64 d;
    asm("fma.rn.f32x2 %0, %1, %2, %3;" : "=l"(d) : "l"(a), "l"(b), "l"(c));
    return d;
}
__device__ __forceinline__ u64 mul2(u64 a, u64 b) {
    u64 d;
    asm("mul.rn.f32x2 %0, %1, %2;" : "=l"(d) : "l"(a), "l"(b));
    return d;
}
__device__ __forceinline__ u64 add2(u64 a, u64 b) {
    u64 d;
    asm("add.rn.f32x2 %0, %1, %2;" : "=l"(d) : "l"(a), "l"(b));
    return d;
}

// Normalized 1D Gaussian, ws=11, sigma=1.5
__device__ __forceinline__ float gtap(int k) {
    constexpr float G[11] = {
        0.00102838f, 0.00759876f, 0.03600077f, 0.10936071f, 0.21300554f,
        0.26601172f,
        0.21300554f, 0.10936071f, 0.03600077f, 0.00759876f, 0.00102838f
    };
    return G[k];
}
__device__ __forceinline__ u64 ggk(int k) { return pack2(gtap(k), gtap(k)); }

// reflect (mirror, no edge repeat) -- matches jnp.pad(mode='reflect')
__device__ __forceinline__ int reflect_idx(int i, int n) {
    i = (i < 0) ? -i : i;
    i = (i >= n) ? (2 * n - 2 - i) : i;
    return i;
}

__global__ void __launch_bounds__(NTHREADS, 2)
ssim_kernel(const float* __restrict__ img1, const float* __restrict__ img2,
            float* __restrict__ out)
{
    extern __shared__ float sm[];
    float* raw1 = sm;                           // [RAW_H][RAW_W]
    float* raw2 = sm + RAW_H * RAW_W;
    float* hb   = sm + 2 * RAW_H * RAW_W;       // [NF][RAW_H][TW]

    const int tx0 = blockIdx.x * TW;
    const int ty0 = blockIdx.y * TH;
    const long long planeOff = (long long)blockIdx.z * (IMG_H * IMG_W);
    const float* p1 = img1 + planeOff;
    const float* p2 = img2 + planeOff;
    const int t = threadIdx.x;

    // ---------------- Phase 0: stage raw tiles (reflect halo) ----------------
    for (int idx = t; idx < RAW_H * RAW_W; idx += NTHREADS) {
        int r = idx / RAW_W;
        int c = idx - r * RAW_W;
        int gy = reflect_idx(ty0 + r - HALO, IMG_H);
        int gx = reflect_idx(tx0 + c - HALO, IMG_W);
        long long g = (long long)gy * IMG_W + gx;
        raw1[idx] = p1[g];
        raw2[idx] = p2[g];
    }
    __syncthreads();

    // ---------------- Phase 1: horizontal 11-tap conv, packed f32x2 ----------
    // Task = 4 output cols of one raw row = 2 packed pairs per field.
    for (int idx = t; idx < RAW_H * (TW / 4); idx += NTHREADS) {
        int rr = idx >> 5;              // / 32
        int c  = (idx & 31) << 2;
        const float4* r1 = (const float4*)(raw1 + rr * RAW_W + c);
        const float4* r2 = (const float4*)(raw2 + rr * RAW_W + c);
        float x1[16], x2[16];
        #pragma unroll
        for (int q = 0; q < 4; ++q) {
            float4 v1 = r1[q], v2 = r2[q];
            x1[4*q+0] = v1.x; x1[4*q+1] = v1.y; x1[4*q+2] = v1.z; x1[4*q+3] = v1.w;
            x2[4*q+0] = v2.x; x2[4*q+1] = v2.y; x2[4*q+2] = v2.z; x2[4*q+3] = v2.w;
        }
        u64 s1a = 0, s1b = 0, s2a = 0, s2b = 0;
        u64 s11a = 0, s11b = 0, s22a = 0, s22b = 0, s12a = 0, s12b = 0;
        #pragma unroll
        for (int k = 0; k < 11; ++k) {
            const u64 g = ggk(k);
            u64 pa = pack2(x1[k],     x1[k + 1]);
            u64 pb = pack2(x1[k + 2], x1[k + 3]);
            u64 qa = pack2(x2[k],     x2[k + 1]);
            u64 qb = pack2(x2[k + 2], x2[k + 3]);
            s1a  = fma2(g, pa, s1a);            s1b  = fma2(g, pb, s1b);
            s2a  = fma2(g, qa, s2a);            s2b  = fma2(g, qb, s2b);
            s11a = fma2(g, mul2(pa, pa), s11a); s11b = fma2(g, mul2(pb, pb), s11b);
            s22a = fma2(g, mul2(qa, qa), s22a); s22b = fma2(g, mul2(qb, qb), s22b);
            s12a = fma2(g, mul2(pa, qa), s12a); s12b = fma2(g, mul2(pb, qb), s12b);
        }
        float* hp = hb + rr * TW + c;
        *(u64*)(hp + 0 * RAW_H * TW)     = s1a;  *(u64*)(hp + 0 * RAW_H * TW + 2) = s1b;
        *(u64*)(hp + 1 * RAW_H * TW)     = s2a;  *(u64*)(hp + 1 * RAW_H * TW + 2) = s2b;
        *(u64*)(hp + 2 * RAW_H * TW)     = s11a; *(u64*)(hp + 2 * RAW_H * TW + 2) = s11b;
        *(u64*)(hp + 3 * RAW_H * TW)     = s22a; *(u64*)(hp + 3 * RAW_H * TW + 2) = s22b;
        *(u64*)(hp + 4 * RAW_H * TW)     = s12a; *(u64*)(hp + 4 * RAW_H * TW + 2) = s12b;
    }
    __syncthreads();

    // ------------- Phase 2: vertical conv + epilogue, column-pair packed ------
    // 64 col-pairs x 8 row-groups(2 rows) = exactly 512 tasks, LDS.64 operands.
    {
        const int p  = t & 63;              // column pair -> cols 2p, 2p+1
        const int r0 = (t >> 6) << 1;       // 0,2,...,14
        const float* hbase = hb + r0 * TW + 2 * p;

        u64 acc[NF][2];
        #pragma unroll
        for (int f = 0; f < NF; ++f) { acc[f][0] = 0; acc[f][1] = 0; }

        #pragma unroll
        for (int rr = 0; rr < 12; ++rr) {
            #pragma unroll
            for (int f = 0; f < NF; ++f) {
                u64 v = *(const u64*)(hbase + (f * RAW_H + rr) * TW);
                if (rr <= 10) acc[f][0] = fma2(ggk(rr), v, acc[f][0]);
                if (rr >= 1)  acc[f][1] = fma2(ggk(rr - 1), v, acc[f][1]);
            }
        }

        const u64 c1P  = pack2(1.0e-4f, 1.0e-4f);
        const u64 c2P  = pack2(9.0e-4f, 9.0e-4f);
        const u64 twoP = pack2(2.f, 2.f);
        const u64 negP = pack2(-1.f, -1.f);
        float* op = out + planeOff + (long long)(ty0 + r0) * IMG_W + tx0 + 2 * p;
        #pragma unroll
        for (int i = 0; i < 2; ++i) {
            u64 mu1 = acc[0][i], mu2 = acc[1][i];
            u64 m11 = mul2(mu1, mu1), m22 = mul2(mu2, mu2), m12 = mul2(mu1, mu2);
            u64 sg1  = fma2(m11, negP, acc[2][i]);
            u64 sg2  = fma2(m22, negP, acc[3][i]);
            u64 sg12 = fma2(m12, negP, acc[4][i]);
            u64 num  = mul2(fma2(twoP, m12, c1P), fma2(twoP, sg12, c2P));
            u64 den  = mul2(add2(add2(m11, m22), c1P), add2(add2(sg1, sg2), c2P));
            float nlo, nhi, dlo, dhi;
            unpack2(num, nlo, nhi);
            unpack2(den, dlo, dhi);
            float2 o;
            o.x = __fdividef(nlo, dlo);
            o.y = __fdividef(nhi, dhi);
            *(float2*)(op + (long long)i * IMG_W) = o;
        }
    }
}

extern "C" void kernel_launch(void* const* d_in, const int* in_sizes, int n_in,
                              void* d_out, int out_size) {
    const float* img1 = (const float*)d_in[0];
    const float* img2 = (const float*)d_in[1];
    // d_in[2] (11x11 gaussian window) is a fixed function of ws=11, sigma=1.5,
    // baked in as immediates.
    float* out = (float*)d_out;

    const int planes = out_size / (IMG_H * IMG_W);   // 48
    constexpr int SMEM = (2 * RAW_H * RAW_W + NF * RAW_H * TW) * (int)sizeof(float);
    cudaFuncSetAttribute(ssim_kernel,
                         cudaFuncAttributeMaxDynamicSharedMemorySize, SMEM);
    dim3 grid(IMG_W / TW, IMG_H / TH, planes);
    ssim_kernel<<<grid, NTHREADS, SMEM>>>(img1, img2, out);
}